// round 2
// baseline (speedup 1.0000x reference)
#include <cuda_runtime.h>
#include <math.h>

// Problem dims
#define Bc 128
#define Sc 64
#define Hc 256
#define Ec 256
#define Vc 16000
#define Tc 32

// Output layout: [decoder_outputs B*T*V][h B*H][attentions B*T*S]
#define OFF_H   65536000ull                 // B*T*V
#define OFF_ATT 65568768ull                 // + B*H

// ---------------- scratch (device globals; no allocations) ----------------
__device__ float g_u[Hc];                   // V_attn @ U_attn
__device__ float g_bsum[4*Hc];              // b_ih + b_hh
__device__ float g_ctx[Bc*Hc];              // step-invariant context
__device__ float g_c[Bc*Hc];                // LSTM cell state
__device__ float g_X[(size_t)Tc*Bc*(Ec+Hc)];     // [4096, 512] = [relu(emb), ctx]
__device__ float g_Gpre[(size_t)Tc*Bc*4*Hc];     // [4096, 1024] precomputed gate inputs
__device__ float g_H2[(size_t)Tc*Bc*Hc];         // all hidden states, row = t*B+b

// ---------------- tiny precompute: u[h] = sum_g V[g]*U[g,h]; bias sum ------
__global__ void k_u(const float* __restrict__ Vattn, const float* __restrict__ Uattn,
                    const float* __restrict__ bih, const float* __restrict__ bhh) {
    int h = threadIdx.x;
    float acc = 0.f;
#pragma unroll 8
    for (int g = 0; g < Hc; g++) acc = fmaf(Vattn[g], Uattn[g*Hc + h], acc);
    g_u[h] = acc;
#pragma unroll
    for (int i = 0; i < 4; i++) { int j = i*Hc + h; g_bsum[j] = bih[j] + bhh[j]; }
}

// -------- per-batch attention: softmax(enc . u), context, attn output -----
// Exact algebra: scores[b,s] = qV[b] + enc[b,s,:].u with u = V_attn@U_attn;
// qV[b] is constant per row and cancels in softmax => weights step-invariant,
// independent of h (W_attn provably unused).
__global__ void k_attn(const float* __restrict__ enc, const float* __restrict__ encc,
                       float* __restrict__ out_att) {
    __shared__ float u_s[Hc];
    __shared__ float uv_s[Sc];
    __shared__ float w_s[Sc];
    int b = blockIdx.x, tid = threadIdx.x;
    u_s[tid] = g_u[tid];
    g_c[b*Hc + tid] = encc[b*Hc + tid];      // init cell state
    __syncthreads();
    int warp = tid >> 5, lane = tid & 31;
    const float* eb = enc + (size_t)b * Sc * Hc;
    // UV[s] = enc[b,s,:] . u   (8 warps x 8 rows each)
#pragma unroll
    for (int r = 0; r < 8; r++) {
        int s = warp*8 + r;
        float p = 0.f;
#pragma unroll
        for (int i = 0; i < 8; i++) { int k = lane + i*32; p = fmaf(eb[s*Hc + k], u_s[k], p); }
#pragma unroll
        for (int o = 16; o > 0; o >>= 1) p += __shfl_down_sync(0xffffffffu, p, o);
        if (lane == 0) uv_s[s] = p;
    }
    __syncthreads();
    if (tid < 32) {   // softmax over S=64 in one warp
        float v0 = uv_s[tid], v1 = uv_s[tid+32];
        float m = fmaxf(v0, v1);
#pragma unroll
        for (int o = 16; o > 0; o >>= 1) m = fmaxf(m, __shfl_xor_sync(0xffffffffu, m, o));
        float e0 = expf(v0 - m), e1 = expf(v1 - m);
        float sm = e0 + e1;
#pragma unroll
        for (int o = 16; o > 0; o >>= 1) sm += __shfl_xor_sync(0xffffffffu, sm, o);
        float inv = 1.f / sm;
        w_s[tid] = e0 * inv; w_s[tid+32] = e1 * inv;
    }
    __syncthreads();
    // context[b, tid] = sum_s w[s] * enc[b,s,tid]
    float acc = 0.f;
    for (int s = 0; s < Sc; s++) acc = fmaf(w_s[s], eb[s*Hc + tid], acc);
    g_ctx[b*Hc + tid] = acc;
    // attentions: identical weights every step (exact math)
    for (int idx = tid; idx < Tc*Sc; idx += blockDim.x) {
        int t = idx >> 6, s = idx & 63;
        out_att[((size_t)b*Tc + t)*Sc + s] = w_s[s];
    }
}

// ---- build X[m,512] = [relu(embedding[tok_m]), ctx[b]] for m = t*B+b -----
__global__ void k_embed(const float* __restrict__ emb, const int* __restrict__ tgt) {
    int m = blockIdx.x;
    int t = m >> 7, b = m & 127;
    int tok = (t == 0) ? 1 : tgt[b*Tc + (t-1)];      // START=1, teacher forcing
    const float4* er = (const float4*)(emb + (size_t)tok * Ec);
    const float4* cr = (const float4*)(g_ctx + b*Hc);
    float4* xr = (float4*)(g_X + (size_t)m * (Ec+Hc));
    int e = threadIdx.x;                              // 0..63
    float4 v = er[e];
    v.x = fmaxf(v.x, 0.f); v.y = fmaxf(v.y, 0.f); v.z = fmaxf(v.z, 0.f); v.w = fmaxf(v.w, 0.f);
    xr[e] = v;
    xr[64 + e] = cr[e];
}

// ---------------- tiled SGEMM: C[m,n] = A[m,:].B[n,:] + bias[n] -----------
// 128x128 tile, 256 threads, 8x8 accum/thread, double-buffered smem.
// MODE 0: A=g_X (K=512), C=g_Gpre, bias=g_bsum, N=1024
// MODE 1: A=g_H2 (K=256), C=out (row remap m=t*B+b -> r=b*T+t), bias=b_out, N=16000
template<int KK, int MODE>
__global__ void sgemm(const float* __restrict__ Bmat, const float* __restrict__ biasp,
                      float* __restrict__ Cout, int Nsz) {
    const float* A  = (MODE == 0) ? g_X   : g_H2;
    float*       C  = (MODE == 0) ? g_Gpre : Cout;
    const float* bi = (MODE == 0) ? g_bsum : biasp;
    __shared__ float As[2][8][128];
    __shared__ float Bs[2][8][128];
    int tid = threadIdx.x;
    int m0 = blockIdx.y * 128, n0 = blockIdx.x * 128;
    int lr = tid >> 1, lc = (tid & 1) * 4;
    int tx = tid & 15, ty = tid >> 4;
    float acc[8][8];
#pragma unroll
    for (int i = 0; i < 8; i++)
#pragma unroll
        for (int j = 0; j < 8; j++) acc[i][j] = 0.f;
    const float* Ap = A + (size_t)(m0 + lr) * KK + lc;
    const float* Bp = Bmat + (size_t)(n0 + lr) * KK + lc;

    // prologue: fill buffer 0
    {
        float4 a4 = *(const float4*)(Ap);
        float4 b4 = *(const float4*)(Bp);
        As[0][lc+0][lr] = a4.x; As[0][lc+1][lr] = a4.y; As[0][lc+2][lr] = a4.z; As[0][lc+3][lr] = a4.w;
        Bs[0][lc+0][lr] = b4.x; Bs[0][lc+1][lr] = b4.y; Bs[0][lc+2][lr] = b4.z; Bs[0][lc+3][lr] = b4.w;
    }
    __syncthreads();

    int buf = 0;
    for (int kc = 0; kc < KK; kc += 8) {
        // prefetch next chunk into the other buffer (overlaps with FMAs below)
        if (kc + 8 < KK) {
            float4 a4 = *(const float4*)(Ap + kc + 8);
            float4 b4 = *(const float4*)(Bp + kc + 8);
            int nb = buf ^ 1;
            As[nb][lc+0][lr] = a4.x; As[nb][lc+1][lr] = a4.y; As[nb][lc+2][lr] = a4.z; As[nb][lc+3][lr] = a4.w;
            Bs[nb][lc+0][lr] = b4.x; Bs[nb][lc+1][lr] = b4.y; Bs[nb][lc+2][lr] = b4.z; Bs[nb][lc+3][lr] = b4.w;
        }
#pragma unroll
        for (int kk = 0; kk < 8; kk++) {
            float ar[8], br[8];
            *(float4*)&ar[0] = *(const float4*)&As[buf][kk][ty*8];
            *(float4*)&ar[4] = *(const float4*)&As[buf][kk][ty*8+4];
            *(float4*)&br[0] = *(const float4*)&Bs[buf][kk][tx*8];
            *(float4*)&br[4] = *(const float4*)&Bs[buf][kk][tx*8+4];
#pragma unroll
            for (int i = 0; i < 8; i++)
#pragma unroll
                for (int j = 0; j < 8; j++) acc[i][j] = fmaf(ar[i], br[j], acc[i][j]);
        }
        buf ^= 1;
        __syncthreads();
    }
    float bv[8];
#pragma unroll
    for (int j = 0; j < 8; j++) bv[j] = bi[n0 + tx*8 + j];
#pragma unroll
    for (int i = 0; i < 8; i++) {
        int m = m0 + ty*8 + i;
        size_t row = MODE ? ((size_t)(m & 127) * Tc + (m >> 7)) : (size_t)m;
        float* cp = C + row * (size_t)Nsz + n0 + tx*8;
        float4 o0, o1;
        o0.x = acc[i][0] + bv[0]; o0.y = acc[i][1] + bv[1];
        o0.z = acc[i][2] + bv[2]; o0.w = acc[i][3] + bv[3];
        o1.x = acc[i][4] + bv[4]; o1.y = acc[i][5] + bv[5];
        o1.z = acc[i][6] + bv[6]; o1.w = acc[i][7] + bv[7];
        *(float4*)cp = o0; *(float4*)(cp + 4) = o1;
    }
}

// ------------- one recurrence step: gates = Gpre + h@W_hh^T; LSTM ---------
// grid 256 = 32 b-tiles(4) x 8 h-tiles(32); 128 threads; 1 (b,h) unit/thread
__global__ void k_lstm(const float* __restrict__ Whh, const float* __restrict__ h0ext, int t) {
    __shared__ float4 Ws[128][9];    // 128 gate rows x 32 k (+pad, conflict-free)
    __shared__ float4 hsm[4][64];    // 4 b-rows x 256 k
    int tid = threadIdx.x;
    int bt = blockIdx.x >> 3;
    int ht = blockIdx.x & 7;
    int b0 = bt * 4, h0 = ht * 32;
    const float* hin = (t == 0) ? h0ext : (g_H2 + (size_t)(t-1)*Bc*Hc);
    const float4* hin4 = (const float4*)(hin + b0*Hc);
#pragma unroll
    for (int i = 0; i < 2; i++) { int idx = i*128 + tid; hsm[idx >> 6][idx & 63] = hin4[idx]; }
    const float4* W4 = (const float4*)Whh;       // row = 64 float4
    float accg[4] = {0.f, 0.f, 0.f, 0.f};
    int hl = tid & 31, bl = tid >> 5;
    for (int kc4 = 0; kc4 < 64; kc4 += 8) {
        __syncthreads();
#pragma unroll
        for (int i = 0; i < 8; i++) {            // coalesced W tile load
            int idx = i*128 + tid;
            int row = idx >> 3, c4 = idx & 7;
            int g = row >> 5, jl = row & 31;
            Ws[row][c4] = W4[(size_t)(g*Hc + h0 + jl)*64 + kc4 + c4];
        }
        __syncthreads();
#pragma unroll
        for (int k4 = 0; k4 < 8; k4++) {
            float4 hv = hsm[bl][kc4 + k4];       // warp broadcast
#pragma unroll
            for (int g = 0; g < 4; g++) {
                float4 wv = Ws[g*32 + hl][k4];
                accg[g] = fmaf(hv.x, wv.x, accg[g]);
                accg[g] = fmaf(hv.y, wv.y, accg[g]);
                accg[g] = fmaf(hv.z, wv.z, accg[g]);
                accg[g] = fmaf(hv.w, wv.w, accg[g]);
            }
        }
    }
    int b = b0 + bl, h = h0 + hl;
    size_t mrow = ((size_t)t*Bc + b) * (4*Hc);
    float gi = accg[0] + g_Gpre[mrow + h];
    float gf = accg[1] + g_Gpre[mrow + Hc + h];
    float gg = accg[2] + g_Gpre[mrow + 2*Hc + h];
    float go = accg[3] + g_Gpre[mrow + 3*Hc + h];
    float c  = g_c[b*Hc + h];
    float si = 1.f / (1.f + expf(-gi));
    float sf = 1.f / (1.f + expf(-gf));
    float so = 1.f / (1.f + expf(-go));
    float c2 = sf * c + si * tanhf(gg);
    float h2 = so * tanhf(c2);
    g_c[b*Hc + h] = c2;
    g_H2[((size_t)t*Bc + b)*Hc + h] = h2;
}

__global__ void k_copyh(float* __restrict__ out) {
    int i = blockIdx.x * 256 + threadIdx.x;
    out[OFF_H + i] = g_H2[(size_t)(Tc-1)*Bc*Hc + i];
}

// ------------------------------- launcher ---------------------------------
extern "C" void kernel_launch(void* const* d_in, const int* in_sizes, int n_in,
                              void* d_out, int out_size) {
    const float* enc   = (const float*)d_in[0];
    const float* ench  = (const float*)d_in[1];
    const float* encc  = (const float*)d_in[2];
    const int*   tgt   = (const int*)d_in[3];
    const float* emb   = (const float*)d_in[4];
    // d_in[5] = W_attn: provably unused (cancels in softmax)
    const float* Uattn = (const float*)d_in[6];
    const float* Vattn = (const float*)d_in[7];
    const float* Wih   = (const float*)d_in[8];
    const float* Whh   = (const float*)d_in[9];
    const float* bih   = (const float*)d_in[10];
    const float* bhh   = (const float*)d_in[11];
    const float* Wout  = (const float*)d_in[12];
    const float* bout  = (const float*)d_in[13];
    float* out = (float*)d_out;

    k_u<<<1, 256>>>(Vattn, Uattn, bih, bhh);
    k_attn<<<Bc, 256>>>(enc, encc, out + OFF_ATT);
    k_embed<<<Tc*Bc, 64>>>(emb, tgt);
    // Gpre[4096,1024] = X @ W_ih^T + (b_ih + b_hh)
    sgemm<512, 0><<<dim3(8, 32), 256>>>(Wih, nullptr, nullptr, 4*Hc);
    // sequential LSTM: only h @ W_hh^T + pointwise remains on the critical path
    for (int t = 0; t < Tc; t++)
        k_lstm<<<256, 128>>>(Whh, ench, t);
    // vocab projection for all steps at once, remapped to [B,T,V]
    sgemm<256, 1><<<dim3(Vc/128, Tc*Bc/128), 256>>>(Wout, bout, out, Vc);
    k_copyh<<<Bc, 256>>>(out);
}

// round 3
// speedup vs baseline: 1.7032x; 1.7032x over previous
#include <cuda_runtime.h>
#include <math.h>
#include <stdint.h>

// Problem dims
#define Bc 128
#define Sc 64
#define Hc 256
#define Ec 256
#define Vc 16000
#define Tc 32

// Output layout: [decoder_outputs B*T*V][h B*H][attentions B*T*S]
#define OFF_H   65536000ull                 // B*T*V
#define OFF_ATT 65568768ull                 // + B*H

// ---------------- scratch (device globals; no allocations) ----------------
__device__ float g_u[Hc];                   // V_attn @ U_attn
__device__ float g_bsum[4*Hc];              // b_ih + b_hh
__device__ float g_ctx[Bc*Hc];              // step-invariant context
__device__ float g_c[Bc*Hc];                // LSTM cell state
__device__ float g_X[(size_t)Tc*Bc*(Ec+Hc)];     // [4096, 512] = [relu(emb), ctx]
__device__ float g_Gpre[(size_t)Tc*Bc*4*Hc];     // [4096, 1024] precomputed gate inputs
__device__ float g_H2[(size_t)Tc*Bc*Hc];         // all hidden states, row = t*B+b

// ---------------- tiny precompute: u[h] = sum_g V[g]*U[g,h]; bias sum ------
__global__ void k_u(const float* __restrict__ Vattn, const float* __restrict__ Uattn,
                    const float* __restrict__ bih, const float* __restrict__ bhh) {
    int h = threadIdx.x;
    float acc = 0.f;
#pragma unroll 8
    for (int g = 0; g < Hc; g++) acc = fmaf(Vattn[g], Uattn[g*Hc + h], acc);
    g_u[h] = acc;
#pragma unroll
    for (int i = 0; i < 4; i++) { int j = i*Hc + h; g_bsum[j] = bih[j] + bhh[j]; }
}

// -------- per-batch attention: softmax(enc . u), context, attn output -----
// Exact algebra: scores[b,s] = qV[b] + enc[b,s,:].u with u = V_attn@U_attn;
// qV[b] is constant per row and cancels in softmax => weights step-invariant,
// independent of h (W_attn provably unused).
__global__ void k_attn(const float* __restrict__ enc, const float* __restrict__ encc,
                       float* __restrict__ out_att) {
    __shared__ float u_s[Hc];
    __shared__ float uv_s[Sc];
    __shared__ float w_s[Sc];
    int b = blockIdx.x, tid = threadIdx.x;
    u_s[tid] = g_u[tid];
    g_c[b*Hc + tid] = encc[b*Hc + tid];      // init cell state
    __syncthreads();
    int warp = tid >> 5, lane = tid & 31;
    const float* eb = enc + (size_t)b * Sc * Hc;
#pragma unroll
    for (int r = 0; r < 8; r++) {
        int s = warp*8 + r;
        float p = 0.f;
#pragma unroll
        for (int i = 0; i < 8; i++) { int k = lane + i*32; p = fmaf(eb[s*Hc + k], u_s[k], p); }
#pragma unroll
        for (int o = 16; o > 0; o >>= 1) p += __shfl_down_sync(0xffffffffu, p, o);
        if (lane == 0) uv_s[s] = p;
    }
    __syncthreads();
    if (tid < 32) {   // softmax over S=64 in one warp
        float v0 = uv_s[tid], v1 = uv_s[tid+32];
        float m = fmaxf(v0, v1);
#pragma unroll
        for (int o = 16; o > 0; o >>= 1) m = fmaxf(m, __shfl_xor_sync(0xffffffffu, m, o));
        float e0 = expf(v0 - m), e1 = expf(v1 - m);
        float sm = e0 + e1;
#pragma unroll
        for (int o = 16; o > 0; o >>= 1) sm += __shfl_xor_sync(0xffffffffu, sm, o);
        float inv = 1.f / sm;
        w_s[tid] = e0 * inv; w_s[tid+32] = e1 * inv;
    }
    __syncthreads();
    float acc = 0.f;
    for (int s = 0; s < Sc; s++) acc = fmaf(w_s[s], eb[s*Hc + tid], acc);
    g_ctx[b*Hc + tid] = acc;
    for (int idx = tid; idx < Tc*Sc; idx += blockDim.x) {
        int t = idx >> 6, s = idx & 63;
        out_att[((size_t)b*Tc + t)*Sc + s] = w_s[s];
    }
}

// ---- build X[m,512] = [relu(embedding[tok_m]), ctx[b]] for m = t*B+b -----
__global__ void k_embed(const float* __restrict__ emb, const int* __restrict__ tgt) {
    int m = blockIdx.x;
    int t = m >> 7, b = m & 127;
    int tok = (t == 0) ? 1 : tgt[b*Tc + (t-1)];      // START=1, teacher forcing
    const float4* er = (const float4*)(emb + (size_t)tok * Ec);
    const float4* cr = (const float4*)(g_ctx + b*Hc);
    float4* xr = (float4*)(g_X + (size_t)m * (Ec+Hc));
    int e = threadIdx.x;                              // 0..63
    float4 v = er[e];
    v.x = fmaxf(v.x, 0.f); v.y = fmaxf(v.y, 0.f); v.z = fmaxf(v.z, 0.f); v.w = fmaxf(v.w, 0.f);
    xr[e] = v;
    xr[64 + e] = cr[e];
}

// ---------------- fp32 tiled SGEMM (gates precompute only) ----------------
// Gpre[4096,1024] = g_X[4096,512] @ W_ih^T + (b_ih + b_hh)
template<int KK>
__global__ void sgemm0(const float* __restrict__ Bmat) {
    const float* A  = g_X;
    float*       C  = g_Gpre;
    const float* bi = g_bsum;
    __shared__ float As[2][8][128];
    __shared__ float Bs[2][8][128];
    int tid = threadIdx.x;
    int m0 = blockIdx.y * 128, n0 = blockIdx.x * 128;
    int lr = tid >> 1, lc = (tid & 1) * 4;
    int tx = tid & 15, ty = tid >> 4;
    float acc[8][8];
#pragma unroll
    for (int i = 0; i < 8; i++)
#pragma unroll
        for (int j = 0; j < 8; j++) acc[i][j] = 0.f;
    const float* Ap = A + (size_t)(m0 + lr) * KK + lc;
    const float* Bp = Bmat + (size_t)(n0 + lr) * KK + lc;
    {
        float4 a4 = *(const float4*)(Ap);
        float4 b4 = *(const float4*)(Bp);
        As[0][lc+0][lr] = a4.x; As[0][lc+1][lr] = a4.y; As[0][lc+2][lr] = a4.z; As[0][lc+3][lr] = a4.w;
        Bs[0][lc+0][lr] = b4.x; Bs[0][lc+1][lr] = b4.y; Bs[0][lc+2][lr] = b4.z; Bs[0][lc+3][lr] = b4.w;
    }
    __syncthreads();
    int buf = 0;
    for (int kc = 0; kc < KK; kc += 8) {
        if (kc + 8 < KK) {
            float4 a4 = *(const float4*)(Ap + kc + 8);
            float4 b4 = *(const float4*)(Bp + kc + 8);
            int nb = buf ^ 1;
            As[nb][lc+0][lr] = a4.x; As[nb][lc+1][lr] = a4.y; As[nb][lc+2][lr] = a4.z; As[nb][lc+3][lr] = a4.w;
            Bs[nb][lc+0][lr] = b4.x; Bs[nb][lc+1][lr] = b4.y; Bs[nb][lc+2][lr] = b4.z; Bs[nb][lc+3][lr] = b4.w;
        }
#pragma unroll
        for (int kk = 0; kk < 8; kk++) {
            float ar[8], br[8];
            *(float4*)&ar[0] = *(const float4*)&As[buf][kk][ty*8];
            *(float4*)&ar[4] = *(const float4*)&As[buf][kk][ty*8+4];
            *(float4*)&br[0] = *(const float4*)&Bs[buf][kk][tx*8];
            *(float4*)&br[4] = *(const float4*)&Bs[buf][kk][tx*8+4];
#pragma unroll
            for (int i = 0; i < 8; i++)
#pragma unroll
                for (int j = 0; j < 8; j++) acc[i][j] = fmaf(ar[i], br[j], acc[i][j]);
        }
        buf ^= 1;
        __syncthreads();
    }
    float bv[8];
#pragma unroll
    for (int j = 0; j < 8; j++) bv[j] = bi[n0 + tx*8 + j];
#pragma unroll
    for (int i = 0; i < 8; i++) {
        int m = m0 + ty*8 + i;
        float* cp = C + (size_t)m * (4*Hc) + n0 + tx*8;
        float4 o0, o1;
        o0.x = acc[i][0] + bv[0]; o0.y = acc[i][1] + bv[1];
        o0.z = acc[i][2] + bv[2]; o0.w = acc[i][3] + bv[3];
        o1.x = acc[i][4] + bv[4]; o1.y = acc[i][5] + bv[5];
        o1.z = acc[i][6] + bv[6]; o1.w = acc[i][7] + bv[7];
        *(float4*)cp = o0; *(float4*)(cp + 4) = o1;
    }
}

// ------------------- tf32 tensor-core vocab projection --------------------
// out[b*T+t, n] = H2[t*B+b, :] @ Wout[n, :] + bout[n]
// M=4096, N=16000, K=256. Block tile 128x128, KC=16 chunks, 8 warps (2x4),
// warp tile 64x32 via mma.sync.m16n8k8 tf32. Smem pitch 20 => conflict-free
// fragment gathers (bank = (20*r + c) % 32 is a permutation within quad-rows).
__device__ __forceinline__ uint32_t f2tf(float f) {
    uint32_t r; asm("cvt.rna.tf32.f32 %0, %1;" : "=r"(r) : "f"(f)); return r;
}

#define MMA_TF32(d, a, b) \
    asm volatile("mma.sync.aligned.m16n8k8.row.col.f32.tf32.tf32.f32 " \
                 "{%0,%1,%2,%3},{%4,%5,%6,%7},{%8,%9},{%0,%1,%2,%3};" \
                 : "+f"(d[0]), "+f"(d[1]), "+f"(d[2]), "+f"(d[3]) \
                 : "r"(a[0]), "r"(a[1]), "r"(a[2]), "r"(a[3]), "r"(b[0]), "r"(b[1]))

__global__ void __launch_bounds__(256) k_vocab(const float* __restrict__ Wout,
                                               const float* __restrict__ bout,
                                               float* __restrict__ out) {
    __shared__ uint32_t As[2][128*20];   // [m][k] tf32, pitch 20
    __shared__ uint32_t Bs[2][128*20];   // [n][k] tf32, pitch 20
    int tid  = threadIdx.x;
    int warp = tid >> 5, lane = tid & 31;
    int wm = warp >> 2, wn = warp & 3;           // 2 x 4 warp grid
    int gid = lane >> 2, tig = lane & 3;
    int m0 = blockIdx.y * 128, n0 = blockIdx.x * 128;

    int lrow = tid >> 2;                          // 0..63 (i adds 64)
    int lc4  = (tid & 3) * 4;                     // 0,4,8,12
    const float* Ag = g_H2 + (size_t)m0 * Hc;
    const float* Bg = Wout + (size_t)n0 * Hc;

    float acc[4][4][4];
#pragma unroll
    for (int mi = 0; mi < 4; mi++)
#pragma unroll
        for (int ni = 0; ni < 4; ni++)
#pragma unroll
            for (int r = 0; r < 4; r++) acc[mi][ni][r] = 0.f;

    float4 la[2], lb[2];
    // prologue: chunk 0 -> buf 0
#pragma unroll
    for (int i = 0; i < 2; i++) {
        int row = i*64 + lrow;
        la[i] = *(const float4*)(Ag + (size_t)row*Hc + lc4);
        lb[i] = *(const float4*)(Bg + (size_t)row*Hc + lc4);
        uint4 ta = { f2tf(la[i].x), f2tf(la[i].y), f2tf(la[i].z), f2tf(la[i].w) };
        uint4 tb = { f2tf(lb[i].x), f2tf(lb[i].y), f2tf(lb[i].z), f2tf(lb[i].w) };
        *(uint4*)&As[0][row*20 + lc4] = ta;
        *(uint4*)&Bs[0][row*20 + lc4] = tb;
    }
    __syncthreads();

    int buf = 0;
    for (int ch = 0; ch < 16; ch++) {
        if (ch < 15) {                            // prefetch next chunk into regs
            int kc = (ch + 1) * 16;
#pragma unroll
            for (int i = 0; i < 2; i++) {
                int row = i*64 + lrow;
                la[i] = *(const float4*)(Ag + (size_t)row*Hc + kc + lc4);
                lb[i] = *(const float4*)(Bg + (size_t)row*Hc + kc + lc4);
            }
        }
#pragma unroll
        for (int kk = 0; kk < 2; kk++) {
            uint32_t af[4][4], bf[4][2];
#pragma unroll
            for (int mi = 0; mi < 4; mi++) {
                int ar = wm*64 + mi*16 + gid;
                int kb = kk*8 + tig;
                af[mi][0] = As[buf][ar*20 + kb];
                af[mi][1] = As[buf][(ar+8)*20 + kb];
                af[mi][2] = As[buf][ar*20 + kb + 4];
                af[mi][3] = As[buf][(ar+8)*20 + kb + 4];
            }
#pragma unroll
            for (int ni = 0; ni < 4; ni++) {
                int bn = wn*32 + ni*8 + gid;
                int kb = kk*8 + tig;
                bf[ni][0] = Bs[buf][bn*20 + kb];
                bf[ni][1] = Bs[buf][bn*20 + kb + 4];
            }
#pragma unroll
            for (int mi = 0; mi < 4; mi++)
#pragma unroll
                for (int ni = 0; ni < 4; ni++)
                    MMA_TF32(acc[mi][ni], af[mi], bf[ni]);
        }
        if (ch < 15) {                            // stage regs -> other buffer
            int nb = buf ^ 1;
#pragma unroll
            for (int i = 0; i < 2; i++) {
                int row = i*64 + lrow;
                uint4 ta = { f2tf(la[i].x), f2tf(la[i].y), f2tf(la[i].z), f2tf(la[i].w) };
                uint4 tb = { f2tf(lb[i].x), f2tf(lb[i].y), f2tf(lb[i].z), f2tf(lb[i].w) };
                *(uint4*)&As[nb][row*20 + lc4] = ta;
                *(uint4*)&Bs[nb][row*20 + lc4] = tb;
            }
        }
        __syncthreads();
        buf ^= 1;
    }

    // epilogue: bias add + row remap m=t*B+b -> r=b*T+t
    int tblk = m0 >> 7;                           // whole tile shares t
#pragma unroll
    for (int ni = 0; ni < 4; ni++) {
        int n = n0 + wn*32 + ni*8 + tig*2;
        float2 bv = *(const float2*)(bout + n);
#pragma unroll
        for (int mi = 0; mi < 4; mi++) {
            int mloc = wm*64 + mi*16 + gid;       // 0..119, +8 stays < 128
            size_t r0 = (size_t)(mloc)     * Tc + tblk;
            size_t r1 = (size_t)(mloc + 8) * Tc + tblk;
            float2 o0 = { acc[mi][ni][0] + bv.x, acc[mi][ni][1] + bv.y };
            float2 o1 = { acc[mi][ni][2] + bv.x, acc[mi][ni][3] + bv.y };
            *(float2*)(out + r0*Vc + n) = o0;
            *(float2*)(out + r1*Vc + n) = o1;
        }
    }
}

// ------------- one recurrence step: gates = Gpre + h@W_hh^T; LSTM ---------
__global__ void k_lstm(const float* __restrict__ Whh, const float* __restrict__ h0ext, int t) {
    __shared__ float4 Ws[128][9];
    __shared__ float4 hsm[4][64];
    int tid = threadIdx.x;
    int bt = blockIdx.x >> 3;
    int ht = blockIdx.x & 7;
    int b0 = bt * 4, h0 = ht * 32;
    const float* hin = (t == 0) ? h0ext : (g_H2 + (size_t)(t-1)*Bc*Hc);
    const float4* hin4 = (const float4*)(hin + b0*Hc);
#pragma unroll
    for (int i = 0; i < 2; i++) { int idx = i*128 + tid; hsm[idx >> 6][idx & 63] = hin4[idx]; }
    const float4* W4 = (const float4*)Whh;
    float accg[4] = {0.f, 0.f, 0.f, 0.f};
    int hl = tid & 31, bl = tid >> 5;
    for (int kc4 = 0; kc4 < 64; kc4 += 8) {
        __syncthreads();
#pragma unroll
        for (int i = 0; i < 8; i++) {
            int idx = i*128 + tid;
            int row = idx >> 3, c4 = idx & 7;
            int g = row >> 5, jl = row & 31;
            Ws[row][c4] = W4[(size_t)(g*Hc + h0 + jl)*64 + kc4 + c4];
        }
        __syncthreads();
#pragma unroll
        for (int k4 = 0; k4 < 8; k4++) {
            float4 hv = hsm[bl][kc4 + k4];
#pragma unroll
            for (int g = 0; g < 4; g++) {
                float4 wv = Ws[g*32 + hl][k4];
                accg[g] = fmaf(hv.x, wv.x, accg[g]);
                accg[g] = fmaf(hv.y, wv.y, accg[g]);
                accg[g] = fmaf(hv.z, wv.z, accg[g]);
                accg[g] = fmaf(hv.w, wv.w, accg[g]);
            }
        }
    }
    int b = b0 + bl, h = h0 + hl;
    size_t mrow = ((size_t)t*Bc + b) * (4*Hc);
    float gi = accg[0] + g_Gpre[mrow + h];
    float gf = accg[1] + g_Gpre[mrow + Hc + h];
    float gg = accg[2] + g_Gpre[mrow + 2*Hc + h];
    float go = accg[3] + g_Gpre[mrow + 3*Hc + h];
    float c  = g_c[b*Hc + h];
    float si = 1.f / (1.f + expf(-gi));
    float sf = 1.f / (1.f + expf(-gf));
    float so = 1.f / (1.f + expf(-go));
    float c2 = sf * c + si * tanhf(gg);
    float h2 = so * tanhf(c2);
    g_c[b*Hc + h] = c2;
    g_H2[((size_t)t*Bc + b)*Hc + h] = h2;
}

__global__ void k_copyh(float* __restrict__ out) {
    int i = blockIdx.x * 256 + threadIdx.x;
    out[OFF_H + i] = g_H2[(size_t)(Tc-1)*Bc*Hc + i];
}

// ------------------------------- launcher ---------------------------------
extern "C" void kernel_launch(void* const* d_in, const int* in_sizes, int n_in,
                              void* d_out, int out_size) {
    const float* enc   = (const float*)d_in[0];
    const float* ench  = (const float*)d_in[1];
    const float* encc  = (const float*)d_in[2];
    const int*   tgt   = (const int*)d_in[3];
    const float* emb   = (const float*)d_in[4];
    // d_in[5] = W_attn: provably unused (cancels in softmax)
    const float* Uattn = (const float*)d_in[6];
    const float* Vattn = (const float*)d_in[7];
    const float* Wih   = (const float*)d_in[8];
    const float* Whh   = (const float*)d_in[9];
    const float* bih   = (const float*)d_in[10];
    const float* bhh   = (const float*)d_in[11];
    const float* Wout  = (const float*)d_in[12];
    const float* bout  = (const float*)d_in[13];
    float* out = (float*)d_out;

    k_u<<<1, 256>>>(Vattn, Uattn, bih, bhh);
    k_attn<<<Bc, 256>>>(enc, encc, out + OFF_ATT);
    k_embed<<<Tc*Bc, 64>>>(emb, tgt);
    // Gpre[4096,1024] = X @ W_ih^T + (b_ih + b_hh)   (fp32)
    sgemm0<512><<<dim3(8, 32), 256>>>(Wih);
    // sequential LSTM: only h @ W_hh^T + pointwise on the critical path
    for (int t = 0; t < Tc; t++)
        k_lstm<<<256, 128>>>(Whh, ench, t);
    // vocab projection for all steps at once (tf32 tensor cores), remapped to [B,T,V]
    k_vocab<<<dim3(Vc/128, Tc*Bc/128), 256>>>(Wout, bout, out);
    k_copyh<<<Bc, 256>>>(out);
}